// round 5
// baseline (speedup 1.0000x reference)
#include <cuda_runtime.h>
#include <cuda_bf16.h>
#include <math.h>
#include <cstdint>

#define BB 32
#define SS 2048
#define FF 128
#define DK 32
#define NROWS (BB*SS)

// Packed projections, 64 bf16 per row (128B): [hi(32) | lo(32)]
// (q pre-scaled by 1/sqrt(32)). Split product: qh.kh + qh.kl + ql.kh
__device__ __nv_bfloat16 g_qp[NROWS*64];
__device__ __nv_bfloat16 g_kp[NROWS*64];
__device__ float g_vw[NROWS*4];            // v_in @ (Wv @ Wo_eff), padded to 4

static __device__ __forceinline__ uint32_t smem_u32(const void* p) {
    uint32_t a;
    asm("{ .reg .u64 t; cvta.to.shared.u64 t, %1; cvt.u32.u64 %0, t; }" : "=r"(a) : "l"(p));
    return a;
}

#define LDSM_X4(r0,r1,r2,r3,addr) \
    asm volatile("ldmatrix.sync.aligned.m8n8.x4.shared.b16 {%0,%1,%2,%3}, [%4];" \
        : "=r"(r0), "=r"(r1), "=r"(r2), "=r"(r3) : "r"(addr))

#define MMA16816(c0,c1,c2,c3,a0,a1,a2,a3,b0,b1) \
    asm volatile("mma.sync.aligned.m16n8k16.row.col.f32.bf16.bf16.f32 " \
        "{%0,%1,%2,%3}, {%4,%5,%6,%7}, {%8,%9}, {%0,%1,%2,%3};" \
        : "+f"(c0), "+f"(c1), "+f"(c2), "+f"(c3) \
        : "r"(a0), "r"(a1), "r"(a2), "r"(a3), "r"(b0), "r"(b1))

// ---------------------------------------------------------------------------
// Projection kernel: grid (NROWS/64, 3). blockIdx.y: 0=Q, 1=K, 2=VW.
// 64 rows per block, 8 rows per thread register-blocked (Q/K phases).
// ---------------------------------------------------------------------------
__global__ __launch_bounds__(256) void proj_kernel(
    const float* __restrict__ qin, const float* __restrict__ kin, const float* __restrict__ vin,
    const float* __restrict__ Wq, const float* __restrict__ bq,
    const float* __restrict__ Wk, const float* __restrict__ bk,
    const float* __restrict__ Wv, const float* __restrict__ Wo) {
    __shared__ float sW[FF*DK];      // 16 KB
    __shared__ float sIn[64*FF];     // 32 KB
    __shared__ float sWoE[DK*3];
    const int tid  = threadIdx.x;
    const int lane = tid & 31;
    const int wr   = tid >> 5;
    const size_t row0 = (size_t)blockIdx.x * 64;
    const int phase = blockIdx.y;

    if (phase < 2) {
        const float* W  = phase ? Wk : Wq;
        const float* bb = phase ? bk : bq;
        const float* in = phase ? kin : qin;
        __nv_bfloat16* gout = phase ? g_kp : g_qp;

        for (int i = tid; i < FF*DK; i += 256) sW[i] = W[i];
        for (int i = tid; i < 2048; i += 256)
            ((float4*)sIn)[i] = ((const float4*)in)[row0*32 + i];
        __syncthreads();

        const int r0r = wr*8;
        float acc[8];
        #pragma unroll
        for (int i = 0; i < 8; ++i) acc[i] = 0.f;

        #pragma unroll 2
        for (int f = 0; f < FF; f += 4) {
            float w0 = sW[(f+0)*DK + lane];
            float w1 = sW[(f+1)*DK + lane];
            float w2 = sW[(f+2)*DK + lane];
            float w3 = sW[(f+3)*DK + lane];
            #pragma unroll
            for (int r = 0; r < 8; ++r) {
                float4 x = *(float4*)&sIn[(r0r + r)*FF + f];
                acc[r] = fmaf(x.x, w0, acc[r]);
                acc[r] = fmaf(x.y, w1, acc[r]);
                acc[r] = fmaf(x.z, w2, acc[r]);
                acc[r] = fmaf(x.w, w3, acc[r]);
            }
        }

        const float bias = bb[lane];
        const float qs = phase ? 1.0f : 0.17677669529663687f;  // 1/sqrt(32) for Q
        #pragma unroll
        for (int r = 0; r < 8; ++r) {
            float v = (acc[r] + bias) * qs;
            __nv_bfloat16 h  = __float2bfloat16(v);
            __nv_bfloat16 lo = __float2bfloat16(v - __bfloat162float(h));
            size_t rr = row0 + r0r + r;
            gout[rr*64 + lane]      = h;
            gout[rr*64 + 32 + lane] = lo;
        }
    } else {
        // VW: v_in @ (Wv @ Wo_eff)
        if (tid < 96) {
            int d = tid / 3, f = tid - d*3;
            float s = 0.f;
            #pragma unroll
            for (int h = 0; h < 16; ++h) s += Wo[(h*DK + d)*3 + f];
            sWoE[tid] = s;
        }
        for (int i = tid; i < 2048; i += 256)
            ((float4*)sIn)[i] = ((const float4*)vin)[row0*32 + i];
        __syncthreads();
        // sW reused as Wv_eff [FF*3]
        for (int i = tid; i < FF*3; i += 256) {
            int r = i / 3, f = i - r*3;
            float s = 0.f;
            #pragma unroll
            for (int d = 0; d < DK; ++d) s = fmaf(Wv[r*DK + d], sWoE[d*3 + f], s);
            sW[i] = s;
        }
        __syncthreads();
        if (tid < 192) {
            int r = tid / 3, f = tid - r*3;
            float s0=0.f,s1=0.f,s2=0.f,s3=0.f;
            #pragma unroll 8
            for (int ff = 0; ff < FF; ff += 4) {
                s0 = fmaf(sIn[r*FF+ff+0], sW[(ff+0)*3+f], s0);
                s1 = fmaf(sIn[r*FF+ff+1], sW[(ff+1)*3+f], s1);
                s2 = fmaf(sIn[r*FF+ff+2], sW[(ff+2)*3+f], s2);
                s3 = fmaf(sIn[r*FF+ff+3], sW[(ff+3)*3+f], s3);
            }
            g_vw[(row0+r)*4 + f] = (s0+s1)+(s2+s3);
        }
    }
}

// ---------------------------------------------------------------------------
// Flash kernel: 128-thread blocks, 4 warps x 32 q-rows (2 m-tiles each).
// Compact [qh|ql] layout: qh fragments reused for both kh and kl B-chunks.
// Two independent 3-MMA chains per tile; no-max softmax; fused 3-col PV.
// ---------------------------------------------------------------------------
#define RSTR 144                       // 9*16 B, odd 16B stride -> conflict-free LDSM
#define SQ_OFF 0
#define SK_OFF (128*RSTR)              // 18432
#define VW_OFF (SK_OFF + 128*RSTR)     // 36864
#define CST_OFF (VW_OFF + 2048)        // 38912
#define SMEM_BYTES (CST_OFF + 16)      // 38928

__global__ __launch_bounds__(128, 5)
void flash5_kernel(float* __restrict__ out,
                   const float* __restrict__ bv,
                   const float* __restrict__ Wo,
                   const float* __restrict__ bo) {
    extern __shared__ __align__(16) unsigned char smem[];
    float* sVW  = (float*)(smem + VW_OFF);
    float* sCST = (float*)(smem + CST_OFF);
    const int tid  = threadIdx.x;
    const int wid  = tid >> 5, lane = tid & 31;
    const size_t base = (size_t)blockIdx.y * SS;
    const int q0 = blockIdx.x * 128;
    const uint32_t sbase = smem_u32(smem);

    if (tid < 3) {
        float s = bo[tid];
        #pragma unroll
        for (int d = 0; d < DK; ++d) {
            float w = 0.f;
            #pragma unroll
            for (int h = 0; h < 16; ++h) w += Wo[(h*DK + d)*3 + tid];
            s = fmaf(bv[d], w, s);
        }
        sCST[tid] = s;
    }

    // Load Q tile: 128 rows x 128B (stride 144)
    for (int i = tid; i < 1024; i += 128) {
        int rr = i >> 3, sg = i & 7;
        *(uint4*)(smem + SQ_OFF + rr*RSTR + sg*16) =
            *(const uint4*)((const unsigned char*)g_qp + (base + q0 + rr)*128 + sg*16);
    }
    __syncthreads();

    const int lr  = lane & 7;
    const int sel = lane >> 3;

    // A fragments (loop-invariant): per m-tile: qh steps {0,1} at +0,+32,
    // ql steps {0,1} at +64,+96.
    uint32_t aF[2][4][4];
    #pragma unroll
    for (int mt = 0; mt < 2; ++mt) {
        int arow = wid*32 + mt*16 + lr + (sel & 1)*8;
        uint32_t abase = sbase + SQ_OFF + arow*RSTR + (sel >> 1)*16;
        #pragma unroll
        for (int g = 0; g < 4; ++g)
            LDSM_X4(aF[mt][g][0], aF[mt][g][1], aF[mt][g][2], aF[mt][g][3], abase + g*32);
    }

    float l[2][2], Ax[2][2], Ay[2][2], Az[2][2];
    #pragma unroll
    for (int mt = 0; mt < 2; ++mt)
        #pragma unroll
        for (int hf = 0; hf < 2; ++hf) {
            l[mt][hf] = 0.f; Ax[mt][hf] = 0.f; Ay[mt][hf] = 0.f; Az[mt][hf] = 0.f;
        }
    const int qc = (lane & 3)*2;

    for (int t = 0; t < 16; ++t) {
        const size_t kbase = base + (size_t)t * 128;
        __syncthreads();
        for (int i = tid; i < 1024; i += 128) {
            int rr = i >> 3, sg = i & 7;
            *(uint4*)(smem + SK_OFF + rr*RSTR + sg*16) =
                *(const uint4*)((const unsigned char*)g_kp + (kbase + rr)*128 + sg*16);
        }
        ((float4*)sVW)[tid] = ((const float4*)g_vw)[kbase + tid];
        __syncthreads();

        #pragma unroll 4
        for (int j = 0; j < 16; ++j) {
            uint32_t bbase = sbase + SK_OFF + (j*8 + lr)*RSTR + sel*16;
            uint32_t bF[8];
            LDSM_X4(bF[0], bF[1], bF[2], bF[3], bbase);        // kh steps 0,1
            LDSM_X4(bF[4], bF[5], bF[6], bF[7], bbase + 64);   // kl steps 0,1

            float4 va = *(float4*)&sVW[(j*8 + qc)*4];
            float4 vb = *(float4*)&sVW[(j*8 + qc + 1)*4];

            #pragma unroll
            for (int mt = 0; mt < 2; ++mt) {
                // chain A: k-step 0 terms; chain B: k-step 1 terms (independent)
                float cA0=0.f, cA1=0.f, cA2=0.f, cA3=0.f;
                float cB0=0.f, cB1=0.f, cB2=0.f, cB3=0.f;
                MMA16816(cA0,cA1,cA2,cA3, aF[mt][0][0],aF[mt][0][1],aF[mt][0][2],aF[mt][0][3], bF[0],bF[1]); // qh.kh0
                MMA16816(cB0,cB1,cB2,cB3, aF[mt][1][0],aF[mt][1][1],aF[mt][1][2],aF[mt][1][3], bF[2],bF[3]); // qh.kh1
                MMA16816(cA0,cA1,cA2,cA3, aF[mt][0][0],aF[mt][0][1],aF[mt][0][2],aF[mt][0][3], bF[4],bF[5]); // qh.kl0
                MMA16816(cB0,cB1,cB2,cB3, aF[mt][1][0],aF[mt][1][1],aF[mt][1][2],aF[mt][1][3], bF[6],bF[7]); // qh.kl1
                MMA16816(cA0,cA1,cA2,cA3, aF[mt][2][0],aF[mt][2][1],aF[mt][2][2],aF[mt][2][3], bF[0],bF[1]); // ql.kh0
                MMA16816(cB0,cB1,cB2,cB3, aF[mt][3][0],aF[mt][3][1],aF[mt][3][2],aF[mt][3][3], bF[2],bF[3]); // ql.kh1

                float p0 = __expf(cA0 + cB0), p1 = __expf(cA1 + cB1);
                float p2 = __expf(cA2 + cB2), p3 = __expf(cA3 + cB3);
                l[mt][0] += p0 + p1;  l[mt][1] += p2 + p3;
                Ax[mt][0] = fmaf(p0, va.x, fmaf(p1, vb.x, Ax[mt][0]));
                Ay[mt][0] = fmaf(p0, va.y, fmaf(p1, vb.y, Ay[mt][0]));
                Az[mt][0] = fmaf(p0, va.z, fmaf(p1, vb.z, Az[mt][0]));
                Ax[mt][1] = fmaf(p2, va.x, fmaf(p3, vb.x, Ax[mt][1]));
                Ay[mt][1] = fmaf(p2, va.y, fmaf(p3, vb.y, Ay[mt][1]));
                Az[mt][1] = fmaf(p2, va.z, fmaf(p3, vb.z, Az[mt][1]));
            }
        }
    }

    // quad-reduce (4 lanes share each q-row) and write
    #pragma unroll
    for (int mt = 0; mt < 2; ++mt)
        #pragma unroll
        for (int hf = 0; hf < 2; ++hf) {
            #pragma unroll
            for (int o = 1; o <= 2; o <<= 1) {
                l[mt][hf]  += __shfl_xor_sync(0xffffffffu, l[mt][hf],  o);
                Ax[mt][hf] += __shfl_xor_sync(0xffffffffu, Ax[mt][hf], o);
                Ay[mt][hf] += __shfl_xor_sync(0xffffffffu, Ay[mt][hf], o);
                Az[mt][hf] += __shfl_xor_sync(0xffffffffu, Az[mt][hf], o);
            }
        }
    if ((lane & 3) == 0) {
        const float c0 = sCST[0], c1 = sCST[1], c2 = sCST[2];
        #pragma unroll
        for (int mt = 0; mt < 2; ++mt)
            #pragma unroll
            for (int hf = 0; hf < 2; ++hf) {
                size_t r = base + q0 + wid*32 + mt*16 + (lane >> 2) + hf*8;
                float inv = 1.0f / l[mt][hf];
                out[r*3 + 0] = fmaf(Ax[mt][hf], inv, c0);
                out[r*3 + 1] = fmaf(Ay[mt][hf], inv, c1);
                out[r*3 + 2] = fmaf(Az[mt][hf], inv, c2);
            }
    }
}

extern "C" void kernel_launch(void* const* d_in, const int* in_sizes, int n_in,
                              void* d_out, int out_size) {
    const float* qin = (const float*)d_in[0];
    const float* kin = (const float*)d_in[1];
    const float* vin = (const float*)d_in[2];
    const float* Wq  = (const float*)d_in[3];
    const float* bq  = (const float*)d_in[4];
    const float* Wk  = (const float*)d_in[5];
    const float* bk  = (const float*)d_in[6];
    const float* Wv  = (const float*)d_in[7];
    const float* bv  = (const float*)d_in[8];
    const float* Wo  = (const float*)d_in[9];
    const float* bo  = (const float*)d_in[10];
    float* out = (float*)d_out;

    cudaFuncSetAttribute(flash5_kernel,
                         cudaFuncAttributeMaxDynamicSharedMemorySize, SMEM_BYTES);
    proj_kernel<<<dim3(NROWS/64, 3), 256>>>(qin, kin, vin, Wq, bq, Wk, bk, Wv, Wo);
    flash5_kernel<<<dim3(SS/128, BB), 128, SMEM_BYTES>>>(out, bv, Wo, bo);
}

// round 6
// speedup vs baseline: 1.1281x; 1.1281x over previous
#include <cuda_runtime.h>
#include <cuda_bf16.h>
#include <math.h>
#include <cstdint>

#define BB 32
#define SS 2048
#define FF 128
#define DK 32
#define NROWS (BB*SS)

// Packed projections, 64 bf16 per row (128B): [hi(32) | lo(32)]
// q pre-scaled by log2(e)/sqrt(32)  (scores computed in log2 domain -> ex2)
__device__ __nv_bfloat16 g_qp[NROWS*64];
__device__ __nv_bfloat16 g_kp[NROWS*64];
__device__ float g_vw[NROWS*4];            // v_in @ (Wv @ Wo_eff), padded to 4

static __device__ __forceinline__ uint32_t smem_u32(const void* p) {
    uint32_t a;
    asm("{ .reg .u64 t; cvta.to.shared.u64 t, %1; cvt.u32.u64 %0, t; }" : "=r"(a) : "l"(p));
    return a;
}
static __device__ __forceinline__ void cp16(uint32_t dst, const void* src) {
    asm volatile("cp.async.cg.shared.global [%0], [%1], 16;" :: "r"(dst), "l"(src) : "memory");
}
#define CP_COMMIT() asm volatile("cp.async.commit_group;" ::: "memory")
#define CP_WAIT(n)  asm volatile("cp.async.wait_group %0;" :: "n"(n) : "memory")

static __device__ __forceinline__ float ex2f(float x) {
    float y; asm("ex2.approx.f32 %0, %1;" : "=f"(y) : "f"(x)); return y;
}

#define LDSM_X4(r0,r1,r2,r3,addr) \
    asm volatile("ldmatrix.sync.aligned.m8n8.x4.shared.b16 {%0,%1,%2,%3}, [%4];" \
        : "=r"(r0), "=r"(r1), "=r"(r2), "=r"(r3) : "r"(addr))

#define MMA16816(c0,c1,c2,c3,a0,a1,a2,a3,b0,b1) \
    asm volatile("mma.sync.aligned.m16n8k16.row.col.f32.bf16.bf16.f32 " \
        "{%0,%1,%2,%3}, {%4,%5,%6,%7}, {%8,%9}, {%0,%1,%2,%3};" \
        : "+f"(c0), "+f"(c1), "+f"(c2), "+f"(c3) \
        : "r"(a0), "r"(a1), "r"(a2), "r"(a3), "r"(b0), "r"(b1))

// ---------------------------------------------------------------------------
// Projection kernel: grid (256, 3). Each block streams 256 rows in 8 chunks
// of 32 with cp.async double-buffering. blockIdx.y: 0=Q, 1=K, 2=VW.
// ---------------------------------------------------------------------------
__global__ __launch_bounds__(256) void proj2_kernel(
    const float* __restrict__ qin, const float* __restrict__ kin, const float* __restrict__ vin,
    const float* __restrict__ Wq, const float* __restrict__ bq,
    const float* __restrict__ Wk, const float* __restrict__ bk,
    const float* __restrict__ Wv, const float* __restrict__ Wo) {
    __shared__ float sW[FF*DK];          // 16 KB (phase2: [0,384)=Wv_eff, [384,480)=WoE)
    __shared__ float sIn[2][32*FF];      // 2 x 16 KB
    const int tid  = threadIdx.x;
    const int lane = tid & 31;
    const int wr   = tid >> 5;
    const int phase = blockIdx.y;
    const size_t row0 = (size_t)blockIdx.x * 256;
    const uint32_t inb0 = smem_u32(&sIn[0][0]);
    const uint32_t inb1 = smem_u32(&sIn[1][0]);

    if (phase < 2) {
        const float* W  = phase ? Wk : Wq;
        const float* bb = phase ? bk : bq;
        const float* in = phase ? kin : qin;
        __nv_bfloat16* gout = phase ? g_kp : g_qp;

        for (int i = tid; i < FF*DK; i += 256) sW[i] = W[i];
        // prologue: chunk 0
        #pragma unroll
        for (int k = 0; k < 4; ++k) {
            int i = tid + k*256;
            cp16(inb0 + i*16, (const float4*)in + row0*32 + i);
        }
        CP_COMMIT();

        const float bias = bb[lane];
        const float qs = phase ? 1.0f
                               : 0.17677669529663687f * 1.4426950408889634f;
        #pragma unroll 1
        for (int c = 0; c < 8; ++c) {
            if (c < 7) {
                uint32_t db = ((c+1) & 1) ? inb1 : inb0;
                #pragma unroll
                for (int k = 0; k < 4; ++k) {
                    int i = tid + k*256;
                    cp16(db + i*16, (const float4*)in + (row0 + (c+1)*32)*32 + i);
                }
                CP_COMMIT();
                CP_WAIT(1);
            } else {
                CP_WAIT(0);
            }
            __syncthreads();

            const float* buf = sIn[c & 1];
            const int r0r = wr*4;
            float a0=0.f, a1=0.f, a2=0.f, a3=0.f;
            #pragma unroll 4
            for (int f = 0; f < FF; f += 4) {
                float w0 = sW[(f+0)*DK + lane];
                float w1 = sW[(f+1)*DK + lane];
                float w2 = sW[(f+2)*DK + lane];
                float w3 = sW[(f+3)*DK + lane];
                float4 x0 = *(const float4*)&buf[(r0r+0)*FF + f];
                float4 x1 = *(const float4*)&buf[(r0r+1)*FF + f];
                float4 x2 = *(const float4*)&buf[(r0r+2)*FF + f];
                float4 x3 = *(const float4*)&buf[(r0r+3)*FF + f];
                a0 = fmaf(x0.x,w0,fmaf(x0.y,w1,fmaf(x0.z,w2,fmaf(x0.w,w3,a0))));
                a1 = fmaf(x1.x,w0,fmaf(x1.y,w1,fmaf(x1.z,w2,fmaf(x1.w,w3,a1))));
                a2 = fmaf(x2.x,w0,fmaf(x2.y,w1,fmaf(x2.z,w2,fmaf(x2.w,w3,a2))));
                a3 = fmaf(x3.x,w0,fmaf(x3.y,w1,fmaf(x3.z,w2,fmaf(x3.w,w3,a3))));
            }
            #pragma unroll
            for (int r = 0; r < 4; ++r) {
                float v = (((r==0)?a0:(r==1)?a1:(r==2)?a2:a3) + bias) * qs;
                __nv_bfloat16 h  = __float2bfloat16(v);
                __nv_bfloat16 lo = __float2bfloat16(v - __bfloat162float(h));
                size_t rr = row0 + c*32 + r0r + r;
                gout[rr*64 + lane]      = h;
                gout[rr*64 + 32 + lane] = lo;
            }
            __syncthreads();
        }
    } else {
        // VW: v_in @ (Wv @ Wo_eff)
        if (tid < 96) {
            int d = tid / 3, f = tid - d*3;
            float s = 0.f;
            #pragma unroll
            for (int h = 0; h < 16; ++h) s += Wo[(h*DK + d)*3 + f];
            sW[384 + tid] = s;
        }
        #pragma unroll
        for (int k = 0; k < 4; ++k) {
            int i = tid + k*256;
            cp16(inb0 + i*16, (const float4*)vin + row0*32 + i);
        }
        CP_COMMIT();
        __syncthreads();
        for (int i = tid; i < FF*3; i += 256) {
            int r = i / 3, f = i - r*3;
            float s = 0.f;
            #pragma unroll
            for (int d = 0; d < DK; ++d) s = fmaf(Wv[r*DK + d], sW[384 + d*3 + f], s);
            sW[i] = s;
        }

        #pragma unroll 1
        for (int c = 0; c < 8; ++c) {
            if (c < 7) {
                uint32_t db = ((c+1) & 1) ? inb1 : inb0;
                #pragma unroll
                for (int k = 0; k < 4; ++k) {
                    int i = tid + k*256;
                    cp16(db + i*16, (const float4*)vin + (row0 + (c+1)*32)*32 + i);
                }
                CP_COMMIT();
                CP_WAIT(1);
            } else {
                CP_WAIT(0);
            }
            __syncthreads();
            if (tid < 96) {
                const float* buf = sIn[c & 1];
                int r = tid / 3, f = tid - r*3;
                float s0=0.f,s1=0.f,s2=0.f,s3=0.f;
                #pragma unroll 8
                for (int ff = 0; ff < FF; ff += 4) {
                    s0 = fmaf(buf[r*FF+ff+0], sW[(ff+0)*3+f], s0);
                    s1 = fmaf(buf[r*FF+ff+1], sW[(ff+1)*3+f], s1);
                    s2 = fmaf(buf[r*FF+ff+2], sW[(ff+2)*3+f], s2);
                    s3 = fmaf(buf[r*FF+ff+3], sW[(ff+3)*3+f], s3);
                }
                g_vw[(row0 + c*32 + r)*4 + f] = (s0+s1)+(s2+s3);
            }
            __syncthreads();
        }
    }
}

// ---------------------------------------------------------------------------
// Flash kernel: 128 threads, 4 warps x 32 q-rows. cp.async double-buffered
// K tiles; vw packed into the K-row padding (RSTR 144 = 128B data + 16B vw).
// No-max softmax in log2 domain (ex2); fused 3-col PV.
// ---------------------------------------------------------------------------
#define RSTR 144
#define TILEB (128*RSTR)               // 18432
#define SQ_OFF 0
#define SK_OFF TILEB                   // buffers at TILEB, 2*TILEB
#define CST_OFF (3*TILEB)              // 55296
#define SMEM_BYTES (CST_OFF + 16)      // 55312

__global__ __launch_bounds__(128, 4)
void flash6_kernel(float* __restrict__ out,
                   const float* __restrict__ bv,
                   const float* __restrict__ Wo,
                   const float* __restrict__ bo) {
    extern __shared__ __align__(16) unsigned char smem[];
    float* sCST = (float*)(smem + CST_OFF);
    const int tid  = threadIdx.x;
    const int wid  = tid >> 5, lane = tid & 31;
    const size_t base = (size_t)blockIdx.y * SS;
    const int q0 = blockIdx.x * 128;
    const uint32_t sbase = smem_u32(smem);

    if (tid < 3) {
        float s = bo[tid];
        #pragma unroll
        for (int d = 0; d < DK; ++d) {
            float w = 0.f;
            #pragma unroll
            for (int h = 0; h < 16; ++h) w += Wo[(h*DK + d)*3 + tid];
            s = fmaf(bv[d], w, s);
        }
        sCST[tid] = s;
    }

    // prologue: Q tile (group 0), K tile 0 (group 1)
    #pragma unroll
    for (int k = 0; k < 8; ++k) {
        int i = tid + k*128;
        int rr = i >> 3, sg = i & 7;
        cp16(sbase + SQ_OFF + rr*RSTR + sg*16,
             (const unsigned char*)g_qp + (base + q0 + rr)*128 + sg*16);
    }
    CP_COMMIT();
    {
        const size_t kb = base;
        #pragma unroll
        for (int k = 0; k < 8; ++k) {
            int i = tid + k*128;
            int rr = i >> 3, sg = i & 7;
            cp16(sbase + SK_OFF + rr*RSTR + sg*16,
                 (const unsigned char*)g_kp + (kb + rr)*128 + sg*16);
        }
        cp16(sbase + SK_OFF + tid*RSTR + 128, g_vw + (kb + tid)*4);
    }
    CP_COMMIT();
    CP_WAIT(1);            // Q ready
    __syncthreads();

    const int lr  = lane & 7;
    const int sel = lane >> 3;

    // A fragments (loop-invariant): qh steps {0,1} then ql steps {0,1}
    uint32_t aF[2][4][4];
    #pragma unroll
    for (int mt = 0; mt < 2; ++mt) {
        int arow = wid*32 + mt*16 + lr + (sel & 1)*8;
        uint32_t abase = sbase + SQ_OFF + arow*RSTR + (sel >> 1)*16;
        #pragma unroll
        for (int g = 0; g < 4; ++g)
            LDSM_X4(aF[mt][g][0], aF[mt][g][1], aF[mt][g][2], aF[mt][g][3], abase + g*32);
    }

    float l[2][2], Ax[2][2], Ay[2][2], Az[2][2];
    #pragma unroll
    for (int mt = 0; mt < 2; ++mt)
        #pragma unroll
        for (int hf = 0; hf < 2; ++hf) {
            l[mt][hf] = 0.f; Ax[mt][hf] = 0.f; Ay[mt][hf] = 0.f; Az[mt][hf] = 0.f;
        }
    const int qc = (lane & 3)*2;

    #pragma unroll 1
    for (int t = 0; t < 16; ++t) {
        if (t < 15) {
            const size_t kb = base + (size_t)(t+1) * 128;
            uint32_t db = sbase + SK_OFF + ((t+1) & 1)*TILEB;
            #pragma unroll
            for (int k = 0; k < 8; ++k) {
                int i = tid + k*128;
                int rr = i >> 3, sg = i & 7;
                cp16(db + rr*RSTR + sg*16,
                     (const unsigned char*)g_kp + (kb + rr)*128 + sg*16);
            }
            cp16(db + tid*RSTR + 128, g_vw + (kb + tid)*4);
            CP_COMMIT();
            CP_WAIT(1);
        } else {
            CP_WAIT(0);
        }
        __syncthreads();

        const uint32_t sk = sbase + SK_OFF + (t & 1)*TILEB;
        #pragma unroll 4
        for (int j = 0; j < 16; ++j) {
            uint32_t bbase = sk + (j*8 + lr)*RSTR + sel*16;
            uint32_t bF[8];
            LDSM_X4(bF[0], bF[1], bF[2], bF[3], bbase);        // kh steps 0,1
            LDSM_X4(bF[4], bF[5], bF[6], bF[7], bbase + 64);   // kl steps 0,1

            float4 va = *(float4*)(smem + (sk - sbase) + (j*8 + qc)*RSTR + 128);
            float4 vb = *(float4*)(smem + (sk - sbase) + (j*8 + qc + 1)*RSTR + 128);

            #pragma unroll
            for (int mt = 0; mt < 2; ++mt) {
                float cA0=0.f, cA1=0.f, cA2=0.f, cA3=0.f;
                float cB0=0.f, cB1=0.f, cB2=0.f, cB3=0.f;
                MMA16816(cA0,cA1,cA2,cA3, aF[mt][0][0],aF[mt][0][1],aF[mt][0][2],aF[mt][0][3], bF[0],bF[1]);
                MMA16816(cB0,cB1,cB2,cB3, aF[mt][1][0],aF[mt][1][1],aF[mt][1][2],aF[mt][1][3], bF[2],bF[3]);
                MMA16816(cA0,cA1,cA2,cA3, aF[mt][0][0],aF[mt][0][1],aF[mt][0][2],aF[mt][0][3], bF[4],bF[5]);
                MMA16816(cB0,cB1,cB2,cB3, aF[mt][1][0],aF[mt][1][1],aF[mt][1][2],aF[mt][1][3], bF[6],bF[7]);
                MMA16816(cA0,cA1,cA2,cA3, aF[mt][2][0],aF[mt][2][1],aF[mt][2][2],aF[mt][2][3], bF[0],bF[1]);
                MMA16816(cB0,cB1,cB2,cB3, aF[mt][3][0],aF[mt][3][1],aF[mt][3][2],aF[mt][3][3], bF[2],bF[3]);

                float p0 = ex2f(cA0 + cB0), p1 = ex2f(cA1 + cB1);
                float p2 = ex2f(cA2 + cB2), p3 = ex2f(cA3 + cB3);
                l[mt][0] += p0 + p1;  l[mt][1] += p2 + p3;
                Ax[mt][0] = fmaf(p0, va.x, fmaf(p1, vb.x, Ax[mt][0]));
                Ay[mt][0] = fmaf(p0, va.y, fmaf(p1, vb.y, Ay[mt][0]));
                Az[mt][0] = fmaf(p0, va.z, fmaf(p1, vb.z, Az[mt][0]));
                Ax[mt][1] = fmaf(p2, va.x, fmaf(p3, vb.x, Ax[mt][1]));
                Ay[mt][1] = fmaf(p2, va.y, fmaf(p3, vb.y, Ay[mt][1]));
                Az[mt][1] = fmaf(p2, va.z, fmaf(p3, vb.z, Az[mt][1]));
            }
        }
        __syncthreads();
    }

    // quad-reduce (4 lanes share each q-row) and write
    #pragma unroll
    for (int mt = 0; mt < 2; ++mt)
        #pragma unroll
        for (int hf = 0; hf < 2; ++hf) {
            #pragma unroll
            for (int o = 1; o <= 2; o <<= 1) {
                l[mt][hf]  += __shfl_xor_sync(0xffffffffu, l[mt][hf],  o);
                Ax[mt][hf] += __shfl_xor_sync(0xffffffffu, Ax[mt][hf], o);
                Ay[mt][hf] += __shfl_xor_sync(0xffffffffu, Ay[mt][hf], o);
                Az[mt][hf] += __shfl_xor_sync(0xffffffffu, Az[mt][hf], o);
            }
        }
    if ((lane & 3) == 0) {
        const float c0 = sCST[0], c1 = sCST[1], c2 = sCST[2];
        #pragma unroll
        for (int mt = 0; mt < 2; ++mt)
            #pragma unroll
            for (int hf = 0; hf < 2; ++hf) {
                size_t r = base + q0 + wid*32 + mt*16 + (lane >> 2) + hf*8;
                float inv = 1.0f / l[mt][hf];
                out[r*3 + 0] = fmaf(Ax[mt][hf], inv, c0);
                out[r*3 + 1] = fmaf(Ay[mt][hf], inv, c1);
                out[r*3 + 2] = fmaf(Az[mt][hf], inv, c2);
            }
    }
}

extern "C" void kernel_launch(void* const* d_in, const int* in_sizes, int n_in,
                              void* d_out, int out_size) {
    const float* qin = (const float*)d_in[0];
    const float* kin = (const float*)d_in[1];
    const float* vin = (const float*)d_in[2];
    const float* Wq  = (const float*)d_in[3];
    const float* bq  = (const float*)d_in[4];
    const float* Wk  = (const float*)d_in[5];
    const float* bk  = (const float*)d_in[6];
    const float* Wv  = (const float*)d_in[7];
    const float* bv  = (const float*)d_in[8];
    const float* Wo  = (const float*)d_in[9];
    const float* bo  = (const float*)d_in[10];
    float* out = (float*)d_out;

    cudaFuncSetAttribute(flash6_kernel,
                         cudaFuncAttributeMaxDynamicSharedMemorySize, SMEM_BYTES);
    proj2_kernel<<<dim3(256, 3), 256>>>(qin, kin, vin, Wq, bq, Wk, bk, Wv, Wo);
    flash6_kernel<<<dim3(SS/128, BB), 128, SMEM_BYTES>>>(out, bv, Wo, bo);
}